// round 1
// baseline (speedup 1.0000x reference)
#include <cuda_runtime.h>
#include <math.h>

// Problem constants
#define BATCH 2
#define SEQ   4096            // 16*16*16
#define CENC  512
#define CDEC  256
#define DFF   1024
#define NHEAD 8
#define HDIM  32
#define MTOT  (BATCH*SEQ)     // 8192

// ---------------- scratch (device globals; no allocation allowed) -------------
__device__ __align__(256) float sQ [MTOT*CDEC];
__device__ __align__(256) float sK [MTOT*CDEC];
__device__ __align__(256) float sV [MTOT*CDEC];
__device__ __align__(256) float sAO[MTOT*CDEC];
__device__ __align__(256) float sX1[MTOT*CDEC];
__device__ __align__(256) float sH [MTOT*DFF];
__device__ __align__(256) float sEncMean[MTOT], sEncRstd[MTOT];
__device__ __align__(256) float sDecMean[MTOT], sDecRstd[MTOT];
__device__ __align__(256) float sM2[MTOT], sR2[MTOT];

__device__ __forceinline__ float gelu_exact(float x) {
    return 0.5f * x * (1.0f + erff(x * 0.70710678118654752f));
}

// ------------- LN stats over channel dim for [B, C, S] layout -----------------
__global__ void col_stats_kernel(const float* __restrict__ x,
                                 float* __restrict__ mean, float* __restrict__ rstd,
                                 int C) {
    int idx = blockIdx.x * blockDim.x + threadIdx.x;   // = b*SEQ + s
    if (idx >= MTOT) return;
    int b = idx >> 12;
    int s = idx & (SEQ - 1);
    const float* xb = x + (size_t)b * C * SEQ + s;
    float sm = 0.f, sq = 0.f;
    for (int c = 0; c < C; c++) {
        float v = xb[(size_t)c << 12];
        sm += v; sq += v * v;
    }
    float m = sm / C;
    mean[idx] = m;
    rstd[idx] = rsqrtf(sq / C - m * m + 1e-5f);
}

// ------------- LN stats over last dim for row-major [M, C] --------------------
__global__ void row_stats_kernel(const float* __restrict__ x,
                                 float* __restrict__ mean, float* __restrict__ rstd,
                                 int C) {
    int row  = blockIdx.x * (blockDim.x >> 5) + (threadIdx.x >> 5);
    int lane = threadIdx.x & 31;
    if (row >= MTOT) return;
    const float* xr = x + (size_t)row * C;
    float s = 0.f, q = 0.f;
    for (int c = lane; c < C; c += 32) { float v = xr[c]; s += v; q += v * v; }
    #pragma unroll
    for (int o = 16; o; o >>= 1) {
        s += __shfl_xor_sync(0xffffffffu, s, o);
        q += __shfl_xor_sync(0xffffffffu, q, o);
    }
    if (lane == 0) {
        float m = s / C;
        mean[row] = m;
        rstd[row] = rsqrtf(q / C - m * m + 1e-5f);
    }
}

// ------------- GEMM with A read from [B, C, S] layout + fused LayerNorm -------
// Y[m, n] = sum_c LN(X[b, c, s]) * W[c, n] + bias[n],  m = b*SEQ + s
__global__ __launch_bounds__(256)
void lngemm_colA_kernel(const float* __restrict__ X,
                        const float* __restrict__ mean, const float* __restrict__ rstd,
                        const float* __restrict__ gamma, const float* __restrict__ beta,
                        const float* __restrict__ W, const float* __restrict__ bias,
                        float* __restrict__ Y, int Kdim, int N) {
    __shared__ __align__(16) float As[16][65];
    __shared__ __align__(16) float Ws[16][64];
    const int tid = threadIdx.x;
    const int m0 = blockIdx.y * 64;
    const int n0 = blockIdx.x * 64;
    const int b  = m0 >> 12;
    const int s0 = m0 & (SEQ - 1);
    const float* Xb = X + (size_t)b * Kdim * SEQ;
    const int tx = tid & 15, ty = tid >> 4;
    const int amm  = tid & 63;
    const int akk0 = tid >> 6;           // 0..3
    const float mA = mean[m0 + amm];
    const float rA = rstd[m0 + amm];
    float acc[4][4] = {};
    for (int k0 = 0; k0 < Kdim; k0 += 16) {
        #pragma unroll
        for (int r = 0; r < 4; r++) {
            int kk = akk0 * 4 + r;
            float xv = Xb[(size_t)(k0 + kk) * SEQ + s0 + amm];
            As[kk][amm] = (xv - mA) * rA * gamma[k0 + kk] + beta[k0 + kk];
        }
        #pragma unroll
        for (int r = 0; r < 4; r++) {
            int kk = akk0 * 4 + r;
            Ws[kk][amm] = W[(size_t)(k0 + kk) * N + n0 + amm];
        }
        __syncthreads();
        #pragma unroll
        for (int kk = 0; kk < 16; kk++) {
            float a0 = As[kk][ty * 4 + 0], a1 = As[kk][ty * 4 + 1];
            float a2 = As[kk][ty * 4 + 2], a3 = As[kk][ty * 4 + 3];
            float4 bv = *(float4*)&Ws[kk][tx * 4];
            acc[0][0] += a0 * bv.x; acc[0][1] += a0 * bv.y; acc[0][2] += a0 * bv.z; acc[0][3] += a0 * bv.w;
            acc[1][0] += a1 * bv.x; acc[1][1] += a1 * bv.y; acc[1][2] += a1 * bv.z; acc[1][3] += a1 * bv.w;
            acc[2][0] += a2 * bv.x; acc[2][1] += a2 * bv.y; acc[2][2] += a2 * bv.z; acc[2][3] += a2 * bv.w;
            acc[3][0] += a3 * bv.x; acc[3][1] += a3 * bv.y; acc[3][2] += a3 * bv.z; acc[3][3] += a3 * bv.w;
        }
        __syncthreads();
    }
    float4 bb = *(const float4*)(bias + n0 + tx * 4);
    #pragma unroll
    for (int i = 0; i < 4; i++) {
        int m = m0 + ty * 4 + i;
        float4 o;
        o.x = acc[i][0] + bb.x; o.y = acc[i][1] + bb.y;
        o.z = acc[i][2] + bb.z; o.w = acc[i][3] + bb.w;
        *(float4*)(Y + (size_t)m * N + n0 + tx * 4) = o;
    }
}

// ------------- GEMM with row-major A, fused epilogues -------------------------
// MODE 0: Y[m,n] = acc + bias[n] + res_colmajor[b, n, s]   (Wo + residual)
// MODE 1: A gets LN (mean/rstd per row, gamma/beta per k); Y = gelu(acc+bias)
// MODE 2: Y written transposed [b, n, s] = acc + bias[n] + res_rowmajor[m, n]
template<int MODE>
__global__ __launch_bounds__(256)
void gemm_rowA_kernel(const float* __restrict__ A, const float* __restrict__ W,
                      const float* __restrict__ bias,
                      const float* __restrict__ mean, const float* __restrict__ rstd,
                      const float* __restrict__ gamma, const float* __restrict__ beta,
                      const float* __restrict__ res, float* __restrict__ Y,
                      int N, int Kdim) {
    __shared__ __align__(16) float As[16][65];
    __shared__ __align__(16) float Ws[16][64];
    const int tid = threadIdx.x;
    const int m0 = blockIdx.y * 64;
    const int n0 = blockIdx.x * 64;
    const int tx = tid & 15, ty = tid >> 4;
    const int akk  = tid & 15;
    const int amm0 = tid >> 4;
    const int wnn  = tid & 63;
    const int wkk0 = tid >> 6;
    float acc[4][4] = {};
    for (int k0 = 0; k0 < Kdim; k0 += 16) {
        #pragma unroll
        for (int r = 0; r < 4; r++) {
            int mm = amm0 + 16 * r;
            float xv = A[(size_t)(m0 + mm) * Kdim + k0 + akk];
            if (MODE == 1)
                xv = (xv - mean[m0 + mm]) * rstd[m0 + mm] * gamma[k0 + akk] + beta[k0 + akk];
            As[akk][mm] = xv;
        }
        #pragma unroll
        for (int r = 0; r < 4; r++) {
            int kk = wkk0 * 4 + r;
            Ws[kk][wnn] = W[(size_t)(k0 + kk) * N + n0 + wnn];
        }
        __syncthreads();
        #pragma unroll
        for (int kk = 0; kk < 16; kk++) {
            float a0 = As[kk][ty * 4 + 0], a1 = As[kk][ty * 4 + 1];
            float a2 = As[kk][ty * 4 + 2], a3 = As[kk][ty * 4 + 3];
            float4 bv = *(float4*)&Ws[kk][tx * 4];
            acc[0][0] += a0 * bv.x; acc[0][1] += a0 * bv.y; acc[0][2] += a0 * bv.z; acc[0][3] += a0 * bv.w;
            acc[1][0] += a1 * bv.x; acc[1][1] += a1 * bv.y; acc[1][2] += a1 * bv.z; acc[1][3] += a1 * bv.w;
            acc[2][0] += a2 * bv.x; acc[2][1] += a2 * bv.y; acc[2][2] += a2 * bv.z; acc[2][3] += a2 * bv.w;
            acc[3][0] += a3 * bv.x; acc[3][1] += a3 * bv.y; acc[3][2] += a3 * bv.z; acc[3][3] += a3 * bv.w;
        }
        __syncthreads();
    }
    const int bIdx = m0 >> 12;
    float4 bb = *(const float4*)(bias + n0 + tx * 4);
    if (MODE == 0) {
        #pragma unroll
        for (int i = 0; i < 4; i++) {
            int m = m0 + ty * 4 + i;
            int s = m & (SEQ - 1);
            float4 o;
            o.x = acc[i][0] + bb.x + res[((size_t)bIdx * N + n0 + tx * 4 + 0) * SEQ + s];
            o.y = acc[i][1] + bb.y + res[((size_t)bIdx * N + n0 + tx * 4 + 1) * SEQ + s];
            o.z = acc[i][2] + bb.z + res[((size_t)bIdx * N + n0 + tx * 4 + 2) * SEQ + s];
            o.w = acc[i][3] + bb.w + res[((size_t)bIdx * N + n0 + tx * 4 + 3) * SEQ + s];
            *(float4*)(Y + (size_t)m * N + n0 + tx * 4) = o;
        }
    } else if (MODE == 1) {
        #pragma unroll
        for (int i = 0; i < 4; i++) {
            int m = m0 + ty * 4 + i;
            float4 o;
            o.x = gelu_exact(acc[i][0] + bb.x);
            o.y = gelu_exact(acc[i][1] + bb.y);
            o.z = gelu_exact(acc[i][2] + bb.z);
            o.w = gelu_exact(acc[i][3] + bb.w);
            *(float4*)(Y + (size_t)m * N + n0 + tx * 4) = o;
        }
    } else {
        int s_base = (m0 & (SEQ - 1)) + ty * 4;
        #pragma unroll
        for (int jj = 0; jj < 4; jj++) {
            int n = n0 + tx * 4 + jj;
            float bj = ((const float*)&bb)[jj];
            float4 o;
            #pragma unroll
            for (int i = 0; i < 4; i++) {
                int m = m0 + ty * 4 + i;
                ((float*)&o)[i] = acc[i][jj] + bj + res[(size_t)m * N + n];
            }
            *(float4*)(Y + ((size_t)bIdx * N + n) * SEQ + s_base) = o;
        }
    }
}

// ------------- Flash attention (fp32, hd=32) -----------------------------------
// grid: (SEQ/64, BATCH*NHEAD), block: 256 threads. 4 lanes per q-row.
__global__ __launch_bounds__(256)
void flash_attn_kernel(const float* __restrict__ Q, const float* __restrict__ K,
                       const float* __restrict__ V, float* __restrict__ O) {
    __shared__ __align__(16) float Qs[64][36];
    __shared__ __align__(16) float Ks[64][36];
    __shared__ __align__(16) float Vs[64][36];
    __shared__ __align__(16) float Ps[64][65];
    const int tid = threadIdx.x;
    const int q   = tid >> 2;          // 0..63
    const int j   = tid & 3;           // 0..3
    const int bh  = blockIdx.y;
    const int b = bh >> 3, h = bh & 7;
    const int q0 = blockIdx.x * 64;
    const float* Qp = Q + (size_t)b * SEQ * CDEC + h * HDIM;
    const float* Kp = K + (size_t)b * SEQ * CDEC + h * HDIM;
    const float* Vp = V + (size_t)b * SEQ * CDEC + h * HDIM;

    {   // load Q tile (64 x 32)
        int r = tid >> 3;
        int c = (tid & 7) * 4;
        #pragma unroll
        for (int rr = 0; rr < 2; rr++)
            *(float4*)&Qs[r + 32 * rr][c] =
                *(const float4*)(Qp + (size_t)(q0 + r + 32 * rr) * CDEC + c);
    }
    __syncthreads();
    float4 qreg[8];
    #pragma unroll
    for (int v = 0; v < 8; v++) qreg[v] = *(float4*)&Qs[q][4 * v];

    float m_i = -1e30f, l_i = 0.f;
    float4 acc0 = {0, 0, 0, 0}, acc1 = {0, 0, 0, 0};
    const float scale = 0.17677669529663687f;  // 1/sqrt(32)

    for (int kt = 0; kt < SEQ / 64; kt++) {
        __syncthreads();
        {
            int r = tid >> 3;
            int c = (tid & 7) * 4;
            #pragma unroll
            for (int rr = 0; rr < 2; rr++) {
                *(float4*)&Ks[r + 32 * rr][c] =
                    *(const float4*)(Kp + (size_t)(kt * 64 + r + 32 * rr) * CDEC + c);
                *(float4*)&Vs[r + 32 * rr][c] =
                    *(const float4*)(Vp + (size_t)(kt * 64 + r + 32 * rr) * CDEC + c);
            }
        }
        __syncthreads();

        float p[16];
        float mloc = -1e30f;
        #pragma unroll
        for (int u = 0; u < 16; u++) {
            int kk = u * 4 + j;
            float4 s4 = {0, 0, 0, 0};
            #pragma unroll
            for (int v = 0; v < 8; v++) {
                float4 k4 = *(float4*)&Ks[kk][4 * v];
                s4.x += qreg[v].x * k4.x; s4.y += qreg[v].y * k4.y;
                s4.z += qreg[v].z * k4.z; s4.w += qreg[v].w * k4.w;
            }
            float s = ((s4.x + s4.y) + (s4.z + s4.w)) * scale;
            p[u] = s;
            mloc = fmaxf(mloc, s);
        }
        mloc = fmaxf(mloc, __shfl_xor_sync(0xffffffffu, mloc, 1, 4));
        mloc = fmaxf(mloc, __shfl_xor_sync(0xffffffffu, mloc, 2, 4));
        float m_new = fmaxf(m_i, mloc);
        float corr = __expf(m_i - m_new);
        float lsum = 0.f;
        #pragma unroll
        for (int u = 0; u < 16; u++) { p[u] = __expf(p[u] - m_new); lsum += p[u]; }
        lsum += __shfl_xor_sync(0xffffffffu, lsum, 1, 4);
        lsum += __shfl_xor_sync(0xffffffffu, lsum, 2, 4);
        l_i = l_i * corr + lsum;
        m_i = m_new;
        acc0.x *= corr; acc0.y *= corr; acc0.z *= corr; acc0.w *= corr;
        acc1.x *= corr; acc1.y *= corr; acc1.z *= corr; acc1.w *= corr;
        #pragma unroll
        for (int u = 0; u < 16; u++) Ps[q][u * 4 + j] = p[u];
        __syncwarp();
        #pragma unroll
        for (int kk = 0; kk < 64; kk++) {
            float pv = Ps[q][kk];
            float4 v0 = *(float4*)&Vs[kk][j * 8];
            float4 v1 = *(float4*)&Vs[kk][j * 8 + 4];
            acc0.x += pv * v0.x; acc0.y += pv * v0.y; acc0.z += pv * v0.z; acc0.w += pv * v0.w;
            acc1.x += pv * v1.x; acc1.y += pv * v1.y; acc1.z += pv * v1.z; acc1.w += pv * v1.w;
        }
    }
    float inv = 1.0f / l_i;
    float* Op = O + ((size_t)b * SEQ + q0 + q) * CDEC + h * HDIM + j * 8;
    float4 o0, o1;
    o0.x = acc0.x * inv; o0.y = acc0.y * inv; o0.z = acc0.z * inv; o0.w = acc0.w * inv;
    o1.x = acc1.x * inv; o1.y = acc1.y * inv; o1.z = acc1.z * inv; o1.w = acc1.w * inv;
    *(float4*)Op = o0;
    *(float4*)(Op + 4) = o1;
}

// ------------------------------ launcher --------------------------------------
extern "C" void kernel_launch(void* const* d_in, const int* in_sizes, int n_in,
                              void* d_out, int out_size) {
    const float* enc   = (const float*)d_in[0];
    const float* dec   = (const float*)d_in[1];
    const float* Wq    = (const float*)d_in[2];
    const float* bq    = (const float*)d_in[3];
    const float* Wk    = (const float*)d_in[4];
    const float* bk    = (const float*)d_in[5];
    const float* Wv    = (const float*)d_in[6];
    const float* bv    = (const float*)d_in[7];
    const float* Wo    = (const float*)d_in[8];
    const float* bo    = (const float*)d_in[9];
    const float* gEnc  = (const float*)d_in[10];
    const float* bEnc  = (const float*)d_in[11];
    const float* gDec  = (const float*)d_in[12];
    const float* bDec  = (const float*)d_in[13];
    const float* gOut  = (const float*)d_in[14];
    const float* bOut  = (const float*)d_in[15];
    const float* W1    = (const float*)d_in[16];
    const float* b1    = (const float*)d_in[17];
    const float* W2    = (const float*)d_in[18];
    const float* b2    = (const float*)d_in[19];
    float* out = (float*)d_out;

    float *pQ, *pK, *pV, *pAO, *pX1, *pH;
    float *pEm, *pEr, *pDm, *pDr, *pM2, *pR2;
    cudaGetSymbolAddress((void**)&pQ,  sQ);
    cudaGetSymbolAddress((void**)&pK,  sK);
    cudaGetSymbolAddress((void**)&pV,  sV);
    cudaGetSymbolAddress((void**)&pAO, sAO);
    cudaGetSymbolAddress((void**)&pX1, sX1);
    cudaGetSymbolAddress((void**)&pH,  sH);
    cudaGetSymbolAddress((void**)&pEm, sEncMean);
    cudaGetSymbolAddress((void**)&pEr, sEncRstd);
    cudaGetSymbolAddress((void**)&pDm, sDecMean);
    cudaGetSymbolAddress((void**)&pDr, sDecRstd);
    cudaGetSymbolAddress((void**)&pM2, sM2);
    cudaGetSymbolAddress((void**)&pR2, sR2);

    // 1. LN statistics (channel dim) for encoder and decoder sequences
    col_stats_kernel<<<64, 128>>>(enc, pEm, pEr, CENC);
    col_stats_kernel<<<64, 128>>>(dec, pDm, pDr, CDEC);

    // 2. Fused LN + projection GEMMs (A read from [B,C,S] layout)
    dim3 gProj(CDEC / 64, MTOT / 64);
    lngemm_colA_kernel<<<gProj, 256>>>(dec, pDm, pDr, gDec, bDec, Wq, bq, pQ, CDEC, CDEC);
    lngemm_colA_kernel<<<gProj, 256>>>(enc, pEm, pEr, gEnc, bEnc, Wk, bk, pK, CENC, CDEC);
    lngemm_colA_kernel<<<gProj, 256>>>(enc, pEm, pEr, gEnc, bEnc, Wv, bv, pV, CENC, CDEC);

    // 3. Flash attention
    flash_attn_kernel<<<dim3(SEQ / 64, BATCH * NHEAD), 256>>>(pQ, pK, pV, pAO);

    // 4. Output projection + residual (residual read from [B,C,S] decoder_feat)
    gemm_rowA_kernel<0><<<dim3(CDEC / 64, MTOT / 64), 256>>>(
        pAO, Wo, bo, nullptr, nullptr, nullptr, nullptr, dec, pX1, CDEC, CDEC);

    // 5. LN2 stats over x1 rows
    row_stats_kernel<<<MTOT / 8, 256>>>(pX1, pM2, pR2, CDEC);

    // 6. FFN1: gelu(LN2(x1) @ W1 + b1)
    gemm_rowA_kernel<1><<<dim3(DFF / 64, MTOT / 64), 256>>>(
        pX1, W1, b1, pM2, pR2, gOut, bOut, nullptr, pH, DFF, CDEC);

    // 7. FFN2 + residual + transposed [B,C,S] output write
    gemm_rowA_kernel<2><<<dim3(CDEC / 64, MTOT / 64), 256>>>(
        pH, W2, b2, nullptr, nullptr, nullptr, nullptr, pX1, out, CDEC, DFF);
}

// round 2
// speedup vs baseline: 2.6263x; 2.6263x over previous
#include <cuda_runtime.h>
#include <math.h>

// Problem constants
#define BATCH 2
#define SEQ   4096            // 16*16*16
#define CENC  512
#define CDEC  256
#define DFF   1024
#define NHEAD 8
#define HDIM  32
#define MTOT  (BATCH*SEQ)     // 8192

// ---------------- scratch (device globals; no allocation allowed) -------------
__device__ __align__(256) float sQ [MTOT*CDEC];
__device__ __align__(256) float sK [MTOT*CDEC];
__device__ __align__(256) float sV [MTOT*CDEC];
__device__ __align__(256) float sAO[MTOT*CDEC];
__device__ __align__(256) float sX1[MTOT*CDEC];
__device__ __align__(256) float sH [MTOT*DFF];
__device__ __align__(256) float sEncMean[MTOT], sEncRstd[MTOT];
__device__ __align__(256) float sDecMean[MTOT], sDecRstd[MTOT];
__device__ __align__(256) float sM2[MTOT], sR2[MTOT];

__device__ __forceinline__ float gelu_exact(float x) {
    return 0.5f * x * (1.0f + erff(x * 0.70710678118654752f));
}

__device__ __forceinline__ unsigned f2tf32(float x) {
    unsigned y; asm("cvt.rna.tf32.f32 %0, %1;" : "=r"(y) : "f"(x)); return y;
}

__device__ __forceinline__ void mma_tf32(float d[4], const unsigned a[4],
                                         const unsigned b[2], const float c[4]) {
    asm volatile(
        "mma.sync.aligned.m16n8k8.row.col.f32.tf32.tf32.f32 "
        "{%0,%1,%2,%3}, {%4,%5,%6,%7}, {%8,%9}, {%10,%11,%12,%13};\n"
        : "=f"(d[0]), "=f"(d[1]), "=f"(d[2]), "=f"(d[3])
        : "r"(a[0]), "r"(a[1]), "r"(a[2]), "r"(a[3]),
          "r"(b[0]), "r"(b[1]),
          "f"(c[0]), "f"(c[1]), "f"(c[2]), "f"(c[3]));
}

// ------------- LN stats over channel dim for [B, C, S] layout -----------------
__global__ void col_stats_kernel(const float* __restrict__ x,
                                 float* __restrict__ mean, float* __restrict__ rstd,
                                 int C) {
    int idx = blockIdx.x * blockDim.x + threadIdx.x;   // = b*SEQ + s
    if (idx >= MTOT) return;
    int b = idx >> 12;
    int s = idx & (SEQ - 1);
    const float* xb = x + (size_t)b * C * SEQ + s;
    float sm = 0.f, sq = 0.f;
    for (int c = 0; c < C; c++) {
        float v = xb[(size_t)c << 12];
        sm += v; sq += v * v;
    }
    float m = sm / C;
    mean[idx] = m;
    rstd[idx] = rsqrtf(sq / C - m * m + 1e-5f);
}

// ------------- LN stats over last dim for row-major [M, C] --------------------
__global__ void row_stats_kernel(const float* __restrict__ x,
                                 float* __restrict__ mean, float* __restrict__ rstd,
                                 int C) {
    int row  = blockIdx.x * (blockDim.x >> 5) + (threadIdx.x >> 5);
    int lane = threadIdx.x & 31;
    if (row >= MTOT) return;
    const float* xr = x + (size_t)row * C;
    float s = 0.f, q = 0.f;
    for (int c = lane; c < C; c += 32) { float v = xr[c]; s += v; q += v * v; }
    #pragma unroll
    for (int o = 16; o; o >>= 1) {
        s += __shfl_xor_sync(0xffffffffu, s, o);
        q += __shfl_xor_sync(0xffffffffu, q, o);
    }
    if (lane == 0) {
        float m = s / C;
        mean[row] = m;
        rstd[row] = rsqrtf(q / C - m * m + 1e-5f);
    }
}

// ------------- GEMM with A read from [B, C, S] layout + fused LayerNorm -------
__global__ __launch_bounds__(256)
void lngemm_colA_kernel(const float* __restrict__ X,
                        const float* __restrict__ mean, const float* __restrict__ rstd,
                        const float* __restrict__ gamma, const float* __restrict__ beta,
                        const float* __restrict__ W, const float* __restrict__ bias,
                        float* __restrict__ Y, int Kdim, int N) {
    __shared__ __align__(16) float As[16][68];
    __shared__ __align__(16) float Ws[16][64];
    const int tid = threadIdx.x;
    const int m0 = blockIdx.y * 64;
    const int n0 = blockIdx.x * 64;
    const int b  = m0 >> 12;
    const int s0 = m0 & (SEQ - 1);
    const float* Xb = X + (size_t)b * Kdim * SEQ;
    const int tx = tid & 15, ty = tid >> 4;
    const int amm  = tid & 63;
    const int akk0 = tid >> 6;           // 0..3
    const float mA = mean[m0 + amm];
    const float rA = rstd[m0 + amm];
    float acc[4][4] = {};
    for (int k0 = 0; k0 < Kdim; k0 += 16) {
        #pragma unroll
        for (int r = 0; r < 4; r++) {
            int kk = akk0 * 4 + r;
            float xv = Xb[(size_t)(k0 + kk) * SEQ + s0 + amm];
            As[kk][amm] = (xv - mA) * rA * gamma[k0 + kk] + beta[k0 + kk];
        }
        #pragma unroll
        for (int r = 0; r < 4; r++) {
            int kk = akk0 * 4 + r;
            Ws[kk][amm] = W[(size_t)(k0 + kk) * N + n0 + amm];
        }
        __syncthreads();
        #pragma unroll
        for (int kk = 0; kk < 16; kk++) {
            float4 av = *(float4*)&As[kk][ty * 4];
            float4 bv = *(float4*)&Ws[kk][tx * 4];
            acc[0][0] += av.x * bv.x; acc[0][1] += av.x * bv.y; acc[0][2] += av.x * bv.z; acc[0][3] += av.x * bv.w;
            acc[1][0] += av.y * bv.x; acc[1][1] += av.y * bv.y; acc[1][2] += av.y * bv.z; acc[1][3] += av.y * bv.w;
            acc[2][0] += av.z * bv.x; acc[2][1] += av.z * bv.y; acc[2][2] += av.z * bv.z; acc[2][3] += av.z * bv.w;
            acc[3][0] += av.w * bv.x; acc[3][1] += av.w * bv.y; acc[3][2] += av.w * bv.z; acc[3][3] += av.w * bv.w;
        }
        __syncthreads();
    }
    float4 bb = *(const float4*)(bias + n0 + tx * 4);
    #pragma unroll
    for (int i = 0; i < 4; i++) {
        int m = m0 + ty * 4 + i;
        float4 o;
        o.x = acc[i][0] + bb.x; o.y = acc[i][1] + bb.y;
        o.z = acc[i][2] + bb.z; o.w = acc[i][3] + bb.w;
        *(float4*)(Y + (size_t)m * N + n0 + tx * 4) = o;
    }
}

// ------------- GEMM with row-major A, fused epilogues -------------------------
// MODE 0: Y[m,n] = acc + bias[n] + res_colmajor[b, n, s]   (Wo + residual)
// MODE 1: A gets LN (mean/rstd per row, gamma/beta per k); Y = gelu(acc+bias)
// MODE 2: Y written transposed [b, n, s] = acc + bias[n] + res_rowmajor[m, n]
template<int MODE>
__global__ __launch_bounds__(256)
void gemm_rowA_kernel(const float* __restrict__ A, const float* __restrict__ W,
                      const float* __restrict__ bias,
                      const float* __restrict__ mean, const float* __restrict__ rstd,
                      const float* __restrict__ gamma, const float* __restrict__ beta,
                      const float* __restrict__ res, float* __restrict__ Y,
                      int N, int Kdim) {
    __shared__ __align__(16) float As[16][68];
    __shared__ __align__(16) float Ws[16][64];
    const int tid = threadIdx.x;
    const int m0 = blockIdx.y * 64;
    const int n0 = blockIdx.x * 64;
    const int tx = tid & 15, ty = tid >> 4;
    const int akk  = tid & 15;
    const int amm0 = tid >> 4;
    const int wnn  = tid & 63;
    const int wkk0 = tid >> 6;
    float acc[4][4] = {};
    for (int k0 = 0; k0 < Kdim; k0 += 16) {
        #pragma unroll
        for (int r = 0; r < 4; r++) {
            int mm = amm0 + 16 * r;
            float xv = A[(size_t)(m0 + mm) * Kdim + k0 + akk];
            if (MODE == 1)
                xv = (xv - mean[m0 + mm]) * rstd[m0 + mm] * gamma[k0 + akk] + beta[k0 + akk];
            As[akk][mm] = xv;
        }
        #pragma unroll
        for (int r = 0; r < 4; r++) {
            int kk = wkk0 * 4 + r;
            Ws[kk][wnn] = W[(size_t)(k0 + kk) * N + n0 + wnn];
        }
        __syncthreads();
        #pragma unroll
        for (int kk = 0; kk < 16; kk++) {
            float4 av = *(float4*)&As[kk][ty * 4];
            float4 bv = *(float4*)&Ws[kk][tx * 4];
            acc[0][0] += av.x * bv.x; acc[0][1] += av.x * bv.y; acc[0][2] += av.x * bv.z; acc[0][3] += av.x * bv.w;
            acc[1][0] += av.y * bv.x; acc[1][1] += av.y * bv.y; acc[1][2] += av.y * bv.z; acc[1][3] += av.y * bv.w;
            acc[2][0] += av.z * bv.x; acc[2][1] += av.z * bv.y; acc[2][2] += av.z * bv.z; acc[2][3] += av.z * bv.w;
            acc[3][0] += av.w * bv.x; acc[3][1] += av.w * bv.y; acc[3][2] += av.w * bv.z; acc[3][3] += av.w * bv.w;
        }
        __syncthreads();
    }
    const int bIdx = m0 >> 12;
    float4 bb = *(const float4*)(bias + n0 + tx * 4);
    if (MODE == 0) {
        #pragma unroll
        for (int i = 0; i < 4; i++) {
            int m = m0 + ty * 4 + i;
            int s = m & (SEQ - 1);
            float4 o;
            o.x = acc[i][0] + bb.x + res[((size_t)bIdx * N + n0 + tx * 4 + 0) * SEQ + s];
            o.y = acc[i][1] + bb.y + res[((size_t)bIdx * N + n0 + tx * 4 + 1) * SEQ + s];
            o.z = acc[i][2] + bb.z + res[((size_t)bIdx * N + n0 + tx * 4 + 2) * SEQ + s];
            o.w = acc[i][3] + bb.w + res[((size_t)bIdx * N + n0 + tx * 4 + 3) * SEQ + s];
            *(float4*)(Y + (size_t)m * N + n0 + tx * 4) = o;
        }
    } else if (MODE == 1) {
        #pragma unroll
        for (int i = 0; i < 4; i++) {
            int m = m0 + ty * 4 + i;
            float4 o;
            o.x = gelu_exact(acc[i][0] + bb.x);
            o.y = gelu_exact(acc[i][1] + bb.y);
            o.z = gelu_exact(acc[i][2] + bb.z);
            o.w = gelu_exact(acc[i][3] + bb.w);
            *(float4*)(Y + (size_t)m * N + n0 + tx * 4) = o;
        }
    } else {
        int s_base = (m0 & (SEQ - 1)) + ty * 4;
        #pragma unroll
        for (int jj = 0; jj < 4; jj++) {
            int n = n0 + tx * 4 + jj;
            float bj = ((const float*)&bb)[jj];
            float4 o;
            #pragma unroll
            for (int i = 0; i < 4; i++) {
                int m = m0 + ty * 4 + i;
                ((float*)&o)[i] = acc[i][jj] + bj + res[(size_t)m * N + n];
            }
            *(float4*)(Y + ((size_t)bIdx * N + n) * SEQ + s_base) = o;
        }
    }
}

// ------------- Flash attention via tf32 mma.sync (hd=32) ----------------------
// grid: (SEQ/64, BATCH*NHEAD), block: 128 threads (4 warps, 16 q-rows per warp)
#define FA_BM 64
#define FA_BN 64
#define KVS   40   // K/V smem row stride (words): conflict-free B-frag loads
#define PSS   72   // P smem row stride (words): conflict-free A-frag loads

__global__ __launch_bounds__(128)
void flash_mma_kernel(const float* __restrict__ Q, const float* __restrict__ K,
                      const float* __restrict__ V, float* __restrict__ O) {
    __shared__ unsigned Ks[FA_BN][KVS];      // tf32 bits
    __shared__ unsigned Vs[FA_BN][KVS];
    __shared__ unsigned Ps[4][16][PSS];      // per-warp P tile (tf32 bits)
    const int tid  = threadIdx.x;
    const int warp = tid >> 5;
    const int lane = tid & 31;
    const int g = lane >> 2, t = lane & 3;
    const int bh = blockIdx.y;
    const int b = bh >> 3, h = bh & 7;
    const int q0 = blockIdx.x * FA_BM;
    const size_t base = (size_t)b * SEQ * CDEC + h * HDIM;
    const float scale = 0.17677669529663687f;  // 1/sqrt(32)

    // Q fragments (A operand), scale folded in. Rows: q0 + warp*16 + {g, g+8}
    unsigned qa[4][4];
    {
        const float* Qp = Q + base + (size_t)(q0 + warp * 16) * CDEC;
        #pragma unroll
        for (int kc = 0; kc < 4; kc++) {
            qa[kc][0] = f2tf32(Qp[(size_t)g       * CDEC + kc * 8 + t]     * scale);
            qa[kc][1] = f2tf32(Qp[(size_t)(g + 8) * CDEC + kc * 8 + t]     * scale);
            qa[kc][2] = f2tf32(Qp[(size_t)g       * CDEC + kc * 8 + t + 4] * scale);
            qa[kc][3] = f2tf32(Qp[(size_t)(g + 8) * CDEC + kc * 8 + t + 4] * scale);
        }
    }

    float m0r = -1e30f, m1r = -1e30f, l0 = 0.f, l1 = 0.f;
    float o[4][4] = {};
    const float* Kp = K + base;
    const float* Vp = V + base;

    for (int kt = 0; kt < SEQ / FA_BN; kt++) {
        __syncthreads();
        {   // load K/V tile (64 x 32) as tf32 into smem
            int r = tid >> 1;
            int c = (tid & 1) * 16;
            const float4* kg = (const float4*)(Kp + (size_t)(kt * FA_BN + r) * CDEC + c);
            const float4* vg = (const float4*)(Vp + (size_t)(kt * FA_BN + r) * CDEC + c);
            #pragma unroll
            for (int i = 0; i < 4; i++) {
                float4 kv = kg[i];
                uint4 kp4 = { f2tf32(kv.x), f2tf32(kv.y), f2tf32(kv.z), f2tf32(kv.w) };
                *(uint4*)&Ks[r][c + 4 * i] = kp4;
                float4 vv = vg[i];
                uint4 vp4 = { f2tf32(vv.x), f2tf32(vv.y), f2tf32(vv.z), f2tf32(vv.w) };
                *(uint4*)&Vs[r][c + 4 * i] = vp4;
            }
        }
        __syncthreads();

        // S = Q * K^T  (per warp: 16 x 64)
        float s[8][4];
        #pragma unroll
        for (int nt = 0; nt < 8; nt++) {
            float c4[4] = {0.f, 0.f, 0.f, 0.f};
            #pragma unroll
            for (int kc = 0; kc < 4; kc++) {
                unsigned bfr[2];
                bfr[0] = Ks[nt * 8 + g][kc * 8 + t];
                bfr[1] = Ks[nt * 8 + g][kc * 8 + t + 4];
                mma_tf32(c4, qa[kc], bfr, c4);
            }
            s[nt][0] = c4[0]; s[nt][1] = c4[1]; s[nt][2] = c4[2]; s[nt][3] = c4[3];
        }

        // online softmax (row g -> c0,c1 ; row g+8 -> c2,c3)
        float mx0 = -1e30f, mx1 = -1e30f;
        #pragma unroll
        for (int nt = 0; nt < 8; nt++) {
            mx0 = fmaxf(mx0, fmaxf(s[nt][0], s[nt][1]));
            mx1 = fmaxf(mx1, fmaxf(s[nt][2], s[nt][3]));
        }
        mx0 = fmaxf(mx0, __shfl_xor_sync(0xffffffffu, mx0, 1));
        mx0 = fmaxf(mx0, __shfl_xor_sync(0xffffffffu, mx0, 2));
        mx1 = fmaxf(mx1, __shfl_xor_sync(0xffffffffu, mx1, 1));
        mx1 = fmaxf(mx1, __shfl_xor_sync(0xffffffffu, mx1, 2));
        float mn0 = fmaxf(m0r, mx0), mn1 = fmaxf(m1r, mx1);
        float corr0 = __expf(m0r - mn0), corr1 = __expf(m1r - mn1);
        float ls0 = 0.f, ls1 = 0.f;
        #pragma unroll
        for (int nt = 0; nt < 8; nt++) {
            float p0 = __expf(s[nt][0] - mn0);
            float p1 = __expf(s[nt][1] - mn0);
            float p2 = __expf(s[nt][2] - mn1);
            float p3 = __expf(s[nt][3] - mn1);
            ls0 += p0 + p1; ls1 += p2 + p3;
            uint2 w0 = { f2tf32(p0), f2tf32(p1) };
            uint2 w1 = { f2tf32(p2), f2tf32(p3) };
            *(uint2*)&Ps[warp][g][nt * 8 + 2 * t]     = w0;
            *(uint2*)&Ps[warp][g + 8][nt * 8 + 2 * t] = w1;
        }
        ls0 += __shfl_xor_sync(0xffffffffu, ls0, 1);
        ls0 += __shfl_xor_sync(0xffffffffu, ls0, 2);
        ls1 += __shfl_xor_sync(0xffffffffu, ls1, 1);
        ls1 += __shfl_xor_sync(0xffffffffu, ls1, 2);
        l0 = l0 * corr0 + ls0;
        l1 = l1 * corr1 + ls1;
        m0r = mn0; m1r = mn1;
        #pragma unroll
        for (int nt = 0; nt < 4; nt++) {
            o[nt][0] *= corr0; o[nt][1] *= corr0;
            o[nt][2] *= corr1; o[nt][3] *= corr1;
        }
        __syncwarp();

        // O += P * V   (per warp: 16 x 32)
        #pragma unroll
        for (int kc = 0; kc < 8; kc++) {
            unsigned pa[4];
            pa[0] = Ps[warp][g][kc * 8 + t];
            pa[1] = Ps[warp][g + 8][kc * 8 + t];
            pa[2] = Ps[warp][g][kc * 8 + t + 4];
            pa[3] = Ps[warp][g + 8][kc * 8 + t + 4];
            #pragma unroll
            for (int nt = 0; nt < 4; nt++) {
                unsigned bfr[2];
                bfr[0] = Vs[kc * 8 + t][nt * 8 + g];
                bfr[1] = Vs[kc * 8 + t + 4][nt * 8 + g];
                mma_tf32(o[nt], pa, bfr, o[nt]);
            }
        }
    }

    float inv0 = 1.0f / l0, inv1 = 1.0f / l1;
    float* Op0 = O + base + (size_t)(q0 + warp * 16 + g) * CDEC;
    float* Op1 = O + base + (size_t)(q0 + warp * 16 + g + 8) * CDEC;
    #pragma unroll
    for (int nt = 0; nt < 4; nt++) {
        float2 r0 = { o[nt][0] * inv0, o[nt][1] * inv0 };
        float2 r1 = { o[nt][2] * inv1, o[nt][3] * inv1 };
        *(float2*)(Op0 + nt * 8 + 2 * t) = r0;
        *(float2*)(Op1 + nt * 8 + 2 * t) = r1;
    }
}

// ------------------------------ launcher --------------------------------------
extern "C" void kernel_launch(void* const* d_in, const int* in_sizes, int n_in,
                              void* d_out, int out_size) {
    const float* enc   = (const float*)d_in[0];
    const float* dec   = (const float*)d_in[1];
    const float* Wq    = (const float*)d_in[2];
    const float* bq    = (const float*)d_in[3];
    const float* Wk    = (const float*)d_in[4];
    const float* bk    = (const float*)d_in[5];
    const float* Wv    = (const float*)d_in[6];
    const float* bv    = (const float*)d_in[7];
    const float* Wo    = (const float*)d_in[8];
    const float* bo    = (const float*)d_in[9];
    const float* gEnc  = (const float*)d_in[10];
    const float* bEnc  = (const float*)d_in[11];
    const float* gDec  = (const float*)d_in[12];
    const float* bDec  = (const float*)d_in[13];
    const float* gOut  = (const float*)d_in[14];
    const float* bOut  = (const float*)d_in[15];
    const float* W1    = (const float*)d_in[16];
    const float* b1    = (const float*)d_in[17];
    const float* W2    = (const float*)d_in[18];
    const float* b2    = (const float*)d_in[19];
    float* out = (float*)d_out;

    float *pQ, *pK, *pV, *pAO, *pX1, *pH;
    float *pEm, *pEr, *pDm, *pDr, *pM2, *pR2;
    cudaGetSymbolAddress((void**)&pQ,  sQ);
    cudaGetSymbolAddress((void**)&pK,  sK);
    cudaGetSymbolAddress((void**)&pV,  sV);
    cudaGetSymbolAddress((void**)&pAO, sAO);
    cudaGetSymbolAddress((void**)&pX1, sX1);
    cudaGetSymbolAddress((void**)&pH,  sH);
    cudaGetSymbolAddress((void**)&pEm, sEncMean);
    cudaGetSymbolAddress((void**)&pEr, sEncRstd);
    cudaGetSymbolAddress((void**)&pDm, sDecMean);
    cudaGetSymbolAddress((void**)&pDr, sDecRstd);
    cudaGetSymbolAddress((void**)&pM2, sM2);
    cudaGetSymbolAddress((void**)&pR2, sR2);

    // 1. LN statistics (channel dim) for encoder and decoder sequences
    col_stats_kernel<<<64, 128>>>(enc, pEm, pEr, CENC);
    col_stats_kernel<<<64, 128>>>(dec, pDm, pDr, CDEC);

    // 2. Fused LN + projection GEMMs (A read from [B,C,S] layout)
    dim3 gProj(CDEC / 64, MTOT / 64);
    lngemm_colA_kernel<<<gProj, 256>>>(dec, pDm, pDr, gDec, bDec, Wq, bq, pQ, CDEC, CDEC);
    lngemm_colA_kernel<<<gProj, 256>>>(enc, pEm, pEr, gEnc, bEnc, Wk, bk, pK, CENC, CDEC);
    lngemm_colA_kernel<<<gProj, 256>>>(enc, pEm, pEr, gEnc, bEnc, Wv, bv, pV, CENC, CDEC);

    // 3. Flash attention (tf32 tensor cores)
    flash_mma_kernel<<<dim3(SEQ / FA_BM, BATCH * NHEAD), 128>>>(pQ, pK, pV, pAO);

    // 4. Output projection + residual (residual read from [B,C,S] decoder_feat)
    gemm_rowA_kernel<0><<<dim3(CDEC / 64, MTOT / 64), 256>>>(
        pAO, Wo, bo, nullptr, nullptr, nullptr, nullptr, dec, pX1, CDEC, CDEC);

    // 5. LN2 stats over x1 rows
    row_stats_kernel<<<MTOT / 8, 256>>>(pX1, pM2, pR2, CDEC);

    // 6. FFN1: gelu(LN2(x1) @ W1 + b1)
    gemm_rowA_kernel<1><<<dim3(DFF / 64, MTOT / 64), 256>>>(
        pX1, W1, b1, pM2, pR2, gOut, bOut, nullptr, pH, DFF, CDEC);

    // 7. FFN2 + residual + transposed [B,C,S] output write
    gemm_rowA_kernel<2><<<dim3(CDEC / 64, MTOT / 64), 256>>>(
        pH, W2, b2, nullptr, nullptr, nullptr, nullptr, pX1, out, CDEC, DFF);
}

// round 3
// speedup vs baseline: 3.1630x; 1.2044x over previous
#include <cuda_runtime.h>
#include <math.h>

// Problem constants
#define BATCH 2
#define SEQ   4096            // 16*16*16
#define CENC  512
#define CDEC  256
#define DFF   1024
#define NHEAD 8
#define HDIM  32
#define MTOT  (BATCH*SEQ)     // 8192

// ---------------- scratch (device globals; no allocation allowed) -------------
__device__ __align__(256) float sQ [MTOT*CDEC];
__device__ __align__(256) float sK [MTOT*CDEC];
__device__ __align__(256) float sV [MTOT*CDEC];
__device__ __align__(256) float sAO[MTOT*CDEC];
__device__ __align__(256) float sX1[MTOT*CDEC];
__device__ __align__(256) float sH [MTOT*DFF];
__device__ __align__(256) float sEncMean[MTOT], sEncRstd[MTOT];
__device__ __align__(256) float sDecMean[MTOT], sDecRstd[MTOT];
__device__ __align__(256) float sM2[MTOT], sR2[MTOT];

__device__ __forceinline__ float gelu_exact(float x) {
    return 0.5f * x * (1.0f + erff(x * 0.70710678118654752f));
}

__device__ __forceinline__ unsigned f2tf32(float x) {
    unsigned y; asm("cvt.rna.tf32.f32 %0, %1;" : "=r"(y) : "f"(x)); return y;
}

__device__ __forceinline__ void mma_tf32(float d[4], const unsigned a[4],
                                         const unsigned b[2], const float c[4]) {
    asm volatile(
        "mma.sync.aligned.m16n8k8.row.col.f32.tf32.tf32.f32 "
        "{%0,%1,%2,%3}, {%4,%5,%6,%7}, {%8,%9}, {%10,%11,%12,%13};\n"
        : "=f"(d[0]), "=f"(d[1]), "=f"(d[2]), "=f"(d[3])
        : "r"(a[0]), "r"(a[1]), "r"(a[2]), "r"(a[3]),
          "r"(b[0]), "r"(b[1]),
          "f"(c[0]), "f"(c[1]), "f"(c[2]), "f"(c[3]));
}

// ------------- LN stats over channel dim for [B, C, S] layout -----------------
__global__ void col_stats_kernel(const float* __restrict__ x,
                                 float* __restrict__ mean, float* __restrict__ rstd,
                                 int C) {
    int idx = blockIdx.x * blockDim.x + threadIdx.x;   // = b*SEQ + s
    if (idx >= MTOT) return;
    int b = idx >> 12;
    int s = idx & (SEQ - 1);
    const float* xb = x + (size_t)b * C * SEQ + s;
    float sm = 0.f, sq = 0.f;
    for (int c = 0; c < C; c++) {
        float v = xb[(size_t)c << 12];
        sm += v; sq += v * v;
    }
    float m = sm / C;
    mean[idx] = m;
    rstd[idx] = rsqrtf(sq / C - m * m + 1e-5f);
}

// ------------- LN stats over last dim for row-major [M, C] --------------------
__global__ void row_stats_kernel(const float* __restrict__ x,
                                 float* __restrict__ mean, float* __restrict__ rstd,
                                 int C) {
    int row  = blockIdx.x * (blockDim.x >> 5) + (threadIdx.x >> 5);
    int lane = threadIdx.x & 31;
    if (row >= MTOT) return;
    const float* xr = x + (size_t)row * C;
    float s = 0.f, q = 0.f;
    for (int c = lane; c < C; c += 32) { float v = xr[c]; s += v; q += v * v; }
    #pragma unroll
    for (int o = 16; o; o >>= 1) {
        s += __shfl_xor_sync(0xffffffffu, s, o);
        q += __shfl_xor_sync(0xffffffffu, q, o);
    }
    if (lane == 0) {
        float m = s / C;
        mean[row] = m;
        rstd[row] = rsqrtf(q / C - m * m + 1e-5f);
    }
}

// ===================== Unified tf32 tensor-core GEMM ==========================
// C[m,n] = sum_k A(m,k) * W[k,n] (+ epilogue)
// AMODE 0: A(m,k) = LN(X[b, k, s]) from [B,C,S] layout (m = b*SEQ+s)
// AMODE 1: A(m,k) = A[m*K+k] (row-major, plain)
// AMODE 2: A(m,k) = LN(A[m*K+k]) (row-major + LN)
// EPI 0: Y[m,n] = acc + bias[n]                       (row-major out)
// EPI 1: Y[m,n] = acc + bias[n] + res[b,n,s]          (res col-major)
// EPI 2: Y[m,n] = gelu(acc + bias[n])
// EPI 3: Y[b,n,s] = acc + bias[n] + res[m,n]          (transposed out)
#define GM_BM 128
#define GM_BN 64
#define GM_BK 16
#define ASTR  136   // ≡8 mod 32 -> conflict-free A-frag reads
#define WSTR  72    // ≡8 mod 32 -> conflict-free B-frag reads

template<int AMODE, int EPI>
__global__ __launch_bounds__(256)
void gemm_mma_kernel(const float* __restrict__ A, const float* __restrict__ W,
                     const float* __restrict__ bias,
                     const float* __restrict__ mean, const float* __restrict__ rstd,
                     const float* __restrict__ gamma, const float* __restrict__ beta,
                     const float* __restrict__ res, float* __restrict__ Y,
                     int Kdim, int N) {
    __shared__ unsigned As[GM_BK][ASTR];
    __shared__ unsigned Ws[GM_BK][WSTR];
    const int tid  = threadIdx.x;
    const int warp = tid >> 5;
    const int lane = tid & 31;
    const int g = lane >> 2, t = lane & 3;
    const int m0 = blockIdx.y * GM_BM;
    const int n0 = blockIdx.x * GM_BN;
    const int bIdx = m0 >> 12;
    const int s0 = m0 & (SEQ - 1);
    const int wm = (warp & 3) * 32;   // warp m-offset in tile
    const int wn = (warp >> 2) * 32;  // warp n-offset in tile

    // A staging indices
    const int mmc = tid & 127;          // colA: m within tile
    const int kkc = tid >> 7;           // colA: k base (0/1)
    const int mmr = tid >> 1;           // rowA: m within tile
    const int ksr = (tid & 1) * 8;      // rowA: k segment
    // W staging indices
    const int wnn = tid & 63;
    const int wk0 = (tid >> 6) * 4;

    float mA = 0.f, rA = 1.f;
    if (AMODE == 0) { mA = mean[m0 + mmc]; rA = rstd[m0 + mmc]; }
    if (AMODE == 2) { mA = mean[m0 + mmr]; rA = rstd[m0 + mmr]; }

    float acc[2][4][4] = {};

    for (int k0 = 0; k0 < Kdim; k0 += GM_BK) {
        // ---- stage A ----
        if (AMODE == 0) {
            const float* Xb = A + (size_t)bIdx * Kdim * SEQ;
            #pragma unroll
            for (int r = 0; r < 8; r++) {
                int kk = kkc + 2 * r;
                float xv = Xb[(size_t)(k0 + kk) * SEQ + s0 + mmc];
                As[kk][mmc] = f2tf32((xv - mA) * rA * __ldg(gamma + k0 + kk)
                                     + __ldg(beta + k0 + kk));
            }
        } else {
            const float4* ap = (const float4*)(A + (size_t)(m0 + mmr) * Kdim + k0 + ksr);
            float4 a0 = ap[0], a1 = ap[1];
            if (AMODE == 2) {
                float4 g0 = *(const float4*)(gamma + k0 + ksr);
                float4 g1 = *(const float4*)(gamma + k0 + ksr + 4);
                float4 e0 = *(const float4*)(beta  + k0 + ksr);
                float4 e1 = *(const float4*)(beta  + k0 + ksr + 4);
                a0.x = (a0.x - mA) * rA * g0.x + e0.x;
                a0.y = (a0.y - mA) * rA * g0.y + e0.y;
                a0.z = (a0.z - mA) * rA * g0.z + e0.z;
                a0.w = (a0.w - mA) * rA * g0.w + e0.w;
                a1.x = (a1.x - mA) * rA * g1.x + e1.x;
                a1.y = (a1.y - mA) * rA * g1.y + e1.y;
                a1.z = (a1.z - mA) * rA * g1.z + e1.z;
                a1.w = (a1.w - mA) * rA * g1.w + e1.w;
            }
            As[ksr + 0][mmr] = f2tf32(a0.x);
            As[ksr + 1][mmr] = f2tf32(a0.y);
            As[ksr + 2][mmr] = f2tf32(a0.z);
            As[ksr + 3][mmr] = f2tf32(a0.w);
            As[ksr + 4][mmr] = f2tf32(a1.x);
            As[ksr + 5][mmr] = f2tf32(a1.y);
            As[ksr + 6][mmr] = f2tf32(a1.z);
            As[ksr + 7][mmr] = f2tf32(a1.w);
        }
        // ---- stage W ----
        #pragma unroll
        for (int r = 0; r < 4; r++) {
            int kk = wk0 + r;
            Ws[kk][wnn] = f2tf32(W[(size_t)(k0 + kk) * N + n0 + wnn]);
        }
        __syncthreads();

        // ---- mma ----
        #pragma unroll
        for (int kc = 0; kc < 2; kc++) {
            unsigned a[2][4];
            #pragma unroll
            for (int mf = 0; mf < 2; mf++) {
                a[mf][0] = As[kc * 8 + t]    [wm + mf * 16 + g];
                a[mf][1] = As[kc * 8 + t]    [wm + mf * 16 + g + 8];
                a[mf][2] = As[kc * 8 + t + 4][wm + mf * 16 + g];
                a[mf][3] = As[kc * 8 + t + 4][wm + mf * 16 + g + 8];
            }
            #pragma unroll
            for (int nf = 0; nf < 4; nf++) {
                unsigned bfr[2];
                bfr[0] = Ws[kc * 8 + t]    [wn + nf * 8 + g];
                bfr[1] = Ws[kc * 8 + t + 4][wn + nf * 8 + g];
                mma_tf32(acc[0][nf], a[0], bfr, acc[0][nf]);
                mma_tf32(acc[1][nf], a[1], bfr, acc[1][nf]);
            }
        }
        __syncthreads();
    }

    // ---- epilogue ----
    #pragma unroll
    for (int mf = 0; mf < 2; mf++) {
        #pragma unroll
        for (int nf = 0; nf < 4; nf++) {
            int col  = n0 + wn + nf * 8 + 2 * t;
            int row0 = m0 + wm + mf * 16 + g;
            int row1 = row0 + 8;
            float bx = bias[col], by = bias[col + 1];
            float c0 = acc[mf][nf][0] + bx, c1 = acc[mf][nf][1] + by;
            float c2 = acc[mf][nf][2] + bx, c3 = acc[mf][nf][3] + by;
            if (EPI == 0) {
                *(float2*)(Y + (size_t)row0 * N + col) = make_float2(c0, c1);
                *(float2*)(Y + (size_t)row1 * N + col) = make_float2(c2, c3);
            } else if (EPI == 1) {
                int sr0 = row0 & (SEQ - 1), sr1 = row1 & (SEQ - 1);
                const float* r0p = res + ((size_t)bIdx * N + col) * SEQ;
                const float* r1p = res + ((size_t)bIdx * N + col + 1) * SEQ;
                c0 += r0p[sr0]; c1 += r1p[sr0];
                c2 += r0p[sr1]; c3 += r1p[sr1];
                *(float2*)(Y + (size_t)row0 * N + col) = make_float2(c0, c1);
                *(float2*)(Y + (size_t)row1 * N + col) = make_float2(c2, c3);
            } else if (EPI == 2) {
                *(float2*)(Y + (size_t)row0 * N + col) =
                    make_float2(gelu_exact(c0), gelu_exact(c1));
                *(float2*)(Y + (size_t)row1 * N + col) =
                    make_float2(gelu_exact(c2), gelu_exact(c3));
            } else {   // EPI 3: transposed write + row-major residual
                int sr0 = row0 & (SEQ - 1), sr1 = row1 & (SEQ - 1);
                float2 rr0 = *(const float2*)(res + (size_t)row0 * N + col);
                float2 rr1 = *(const float2*)(res + (size_t)row1 * N + col);
                float* y0 = Y + ((size_t)bIdx * N + col) * SEQ;
                float* y1 = Y + ((size_t)bIdx * N + col + 1) * SEQ;
                y0[sr0] = c0 + rr0.x;  y1[sr0] = c1 + rr0.y;
                y0[sr1] = c2 + rr1.x;  y1[sr1] = c3 + rr1.y;
            }
        }
    }
}

// ------------- Flash attention via tf32 mma.sync (hd=32) ----------------------
#define FA_BM 64
#define FA_BN 64
#define KVS   40
#define PSS   72

__global__ __launch_bounds__(128)
void flash_mma_kernel(const float* __restrict__ Q, const float* __restrict__ K,
                      const float* __restrict__ V, float* __restrict__ O) {
    __shared__ unsigned Ks[FA_BN][KVS];
    __shared__ unsigned Vs[FA_BN][KVS];
    __shared__ unsigned Ps[4][16][PSS];
    const int tid  = threadIdx.x;
    const int warp = tid >> 5;
    const int lane = tid & 31;
    const int g = lane >> 2, t = lane & 3;
    const int bh = blockIdx.y;
    const int b = bh >> 3, h = bh & 7;
    const int q0 = blockIdx.x * FA_BM;
    const size_t base = (size_t)b * SEQ * CDEC + h * HDIM;
    const float scale = 0.17677669529663687f;

    unsigned qa[4][4];
    {
        const float* Qp = Q + base + (size_t)(q0 + warp * 16) * CDEC;
        #pragma unroll
        for (int kc = 0; kc < 4; kc++) {
            qa[kc][0] = f2tf32(Qp[(size_t)g       * CDEC + kc * 8 + t]     * scale);
            qa[kc][1] = f2tf32(Qp[(size_t)(g + 8) * CDEC + kc * 8 + t]     * scale);
            qa[kc][2] = f2tf32(Qp[(size_t)g       * CDEC + kc * 8 + t + 4] * scale);
            qa[kc][3] = f2tf32(Qp[(size_t)(g + 8) * CDEC + kc * 8 + t + 4] * scale);
        }
    }

    float m0r = -1e30f, m1r = -1e30f, l0 = 0.f, l1 = 0.f;
    float o[4][4] = {};
    const float* Kp = K + base;
    const float* Vp = V + base;

    for (int kt = 0; kt < SEQ / FA_BN; kt++) {
        __syncthreads();
        {
            int r = tid >> 1;
            int c = (tid & 1) * 16;
            const float4* kg = (const float4*)(Kp + (size_t)(kt * FA_BN + r) * CDEC + c);
            const float4* vg = (const float4*)(Vp + (size_t)(kt * FA_BN + r) * CDEC + c);
            #pragma unroll
            for (int i = 0; i < 4; i++) {
                float4 kv = kg[i];
                uint4 kp4 = { f2tf32(kv.x), f2tf32(kv.y), f2tf32(kv.z), f2tf32(kv.w) };
                *(uint4*)&Ks[r][c + 4 * i] = kp4;
                float4 vv = vg[i];
                uint4 vp4 = { f2tf32(vv.x), f2tf32(vv.y), f2tf32(vv.z), f2tf32(vv.w) };
                *(uint4*)&Vs[r][c + 4 * i] = vp4;
            }
        }
        __syncthreads();

        float s[8][4];
        #pragma unroll
        for (int nt = 0; nt < 8; nt++) {
            float c4[4] = {0.f, 0.f, 0.f, 0.f};
            #pragma unroll
            for (int kc = 0; kc < 4; kc++) {
                unsigned bfr[2];
                bfr[0] = Ks[nt * 8 + g][kc * 8 + t];
                bfr[1] = Ks[nt * 8 + g][kc * 8 + t + 4];
                mma_tf32(c4, qa[kc], bfr, c4);
            }
            s[nt][0] = c4[0]; s[nt][1] = c4[1]; s[nt][2] = c4[2]; s[nt][3] = c4[3];
        }

        float mx0 = -1e30f, mx1 = -1e30f;
        #pragma unroll
        for (int nt = 0; nt < 8; nt++) {
            mx0 = fmaxf(mx0, fmaxf(s[nt][0], s[nt][1]));
            mx1 = fmaxf(mx1, fmaxf(s[nt][2], s[nt][3]));
        }
        mx0 = fmaxf(mx0, __shfl_xor_sync(0xffffffffu, mx0, 1));
        mx0 = fmaxf(mx0, __shfl_xor_sync(0xffffffffu, mx0, 2));
        mx1 = fmaxf(mx1, __shfl_xor_sync(0xffffffffu, mx1, 1));
        mx1 = fmaxf(mx1, __shfl_xor_sync(0xffffffffu, mx1, 2));
        float mn0 = fmaxf(m0r, mx0), mn1 = fmaxf(m1r, mx1);
        float corr0 = __expf(m0r - mn0), corr1 = __expf(m1r - mn1);
        float ls0 = 0.f, ls1 = 0.f;
        #pragma unroll
        for (int nt = 0; nt < 8; nt++) {
            float p0 = __expf(s[nt][0] - mn0);
            float p1 = __expf(s[nt][1] - mn0);
            float p2 = __expf(s[nt][2] - mn1);
            float p3 = __expf(s[nt][3] - mn1);
            ls0 += p0 + p1; ls1 += p2 + p3;
            uint2 w0 = { f2tf32(p0), f2tf32(p1) };
            uint2 w1 = { f2tf32(p2), f2tf32(p3) };
            *(uint2*)&Ps[warp][g][nt * 8 + 2 * t]     = w0;
            *(uint2*)&Ps[warp][g + 8][nt * 8 + 2 * t] = w1;
        }
        ls0 += __shfl_xor_sync(0xffffffffu, ls0, 1);
        ls0 += __shfl_xor_sync(0xffffffffu, ls0, 2);
        ls1 += __shfl_xor_sync(0xffffffffu, ls1, 1);
        ls1 += __shfl_xor_sync(0xffffffffu, ls1, 2);
        l0 = l0 * corr0 + ls0;
        l1 = l1 * corr1 + ls1;
        m0r = mn0; m1r = mn1;
        #pragma unroll
        for (int nt = 0; nt < 4; nt++) {
            o[nt][0] *= corr0; o[nt][1] *= corr0;
            o[nt][2] *= corr1; o[nt][3] *= corr1;
        }
        __syncwarp();

        #pragma unroll
        for (int kc = 0; kc < 8; kc++) {
            unsigned pa[4];
            pa[0] = Ps[warp][g][kc * 8 + t];
            pa[1] = Ps[warp][g + 8][kc * 8 + t];
            pa[2] = Ps[warp][g][kc * 8 + t + 4];
            pa[3] = Ps[warp][g + 8][kc * 8 + t + 4];
            #pragma unroll
            for (int nt = 0; nt < 4; nt++) {
                unsigned bfr[2];
                bfr[0] = Vs[kc * 8 + t][nt * 8 + g];
                bfr[1] = Vs[kc * 8 + t + 4][nt * 8 + g];
                mma_tf32(o[nt], pa, bfr, o[nt]);
            }
        }
    }

    float inv0 = 1.0f / l0, inv1 = 1.0f / l1;
    float* Op0 = O + base + (size_t)(q0 + warp * 16 + g) * CDEC;
    float* Op1 = O + base + (size_t)(q0 + warp * 16 + g + 8) * CDEC;
    #pragma unroll
    for (int nt = 0; nt < 4; nt++) {
        float2 r0 = { o[nt][0] * inv0, o[nt][1] * inv0 };
        float2 r1 = { o[nt][2] * inv1, o[nt][3] * inv1 };
        *(float2*)(Op0 + nt * 8 + 2 * t) = r0;
        *(float2*)(Op1 + nt * 8 + 2 * t) = r1;
    }
}

// ------------------------------ launcher --------------------------------------
extern "C" void kernel_launch(void* const* d_in, const int* in_sizes, int n_in,
                              void* d_out, int out_size) {
    const float* enc   = (const float*)d_in[0];
    const float* dec   = (const float*)d_in[1];
    const float* Wq    = (const float*)d_in[2];
    const float* bq    = (const float*)d_in[3];
    const float* Wk    = (const float*)d_in[4];
    const float* bk    = (const float*)d_in[5];
    const float* Wv    = (const float*)d_in[6];
    const float* bv    = (const float*)d_in[7];
    const float* Wo    = (const float*)d_in[8];
    const float* bo    = (const float*)d_in[9];
    const float* gEnc  = (const float*)d_in[10];
    const float* bEnc  = (const float*)d_in[11];
    const float* gDec  = (const float*)d_in[12];
    const float* bDec  = (const float*)d_in[13];
    const float* gOut  = (const float*)d_in[14];
    const float* bOut  = (const float*)d_in[15];
    const float* W1    = (const float*)d_in[16];
    const float* b1    = (const float*)d_in[17];
    const float* W2    = (const float*)d_in[18];
    const float* b2    = (const float*)d_in[19];
    float* out = (float*)d_out;

    float *pQ, *pK, *pV, *pAO, *pX1, *pH;
    float *pEm, *pEr, *pDm, *pDr, *pM2, *pR2;
    cudaGetSymbolAddress((void**)&pQ,  sQ);
    cudaGetSymbolAddress((void**)&pK,  sK);
    cudaGetSymbolAddress((void**)&pV,  sV);
    cudaGetSymbolAddress((void**)&pAO, sAO);
    cudaGetSymbolAddress((void**)&pX1, sX1);
    cudaGetSymbolAddress((void**)&pH,  sH);
    cudaGetSymbolAddress((void**)&pEm, sEncMean);
    cudaGetSymbolAddress((void**)&pEr, sEncRstd);
    cudaGetSymbolAddress((void**)&pDm, sDecMean);
    cudaGetSymbolAddress((void**)&pDr, sDecRstd);
    cudaGetSymbolAddress((void**)&pM2, sM2);
    cudaGetSymbolAddress((void**)&pR2, sR2);

    // 1. LN statistics (channel dim) for encoder and decoder sequences
    col_stats_kernel<<<64, 128>>>(enc, pEm, pEr, CENC);
    col_stats_kernel<<<64, 128>>>(dec, pDm, pDr, CDEC);

    // 2. Fused LN + projection GEMMs (tf32 mma, A from [B,C,S] layout)
    dim3 gProj(CDEC / GM_BN, MTOT / GM_BM);
    gemm_mma_kernel<0,0><<<gProj, 256>>>(dec, Wq, bq, pDm, pDr, gDec, bDec, nullptr, pQ, CDEC, CDEC);
    gemm_mma_kernel<0,0><<<gProj, 256>>>(enc, Wk, bk, pEm, pEr, gEnc, bEnc, nullptr, pK, CENC, CDEC);
    gemm_mma_kernel<0,0><<<gProj, 256>>>(enc, Wv, bv, pEm, pEr, gEnc, bEnc, nullptr, pV, CENC, CDEC);

    // 3. Flash attention (tf32 tensor cores)
    flash_mma_kernel<<<dim3(SEQ / FA_BM, BATCH * NHEAD), 128>>>(pQ, pK, pV, pAO);

    // 4. Output projection + residual (residual read from [B,C,S] decoder_feat)
    gemm_mma_kernel<1,1><<<dim3(CDEC / GM_BN, MTOT / GM_BM), 256>>>(
        pAO, Wo, bo, nullptr, nullptr, nullptr, nullptr, dec, pX1, CDEC, CDEC);

    // 5. LN2 stats over x1 rows
    row_stats_kernel<<<MTOT / 8, 256>>>(pX1, pM2, pR2, CDEC);

    // 6. FFN1: gelu(LN2(x1) @ W1 + b1)
    gemm_mma_kernel<2,2><<<dim3(DFF / GM_BN, MTOT / GM_BM), 256>>>(
        pX1, W1, b1, pM2, pR2, gOut, bOut, nullptr, pH, CDEC, DFF);

    // 7. FFN2 + residual + transposed [B,C,S] output write
    gemm_mma_kernel<1,3><<<dim3(CDEC / GM_BN, MTOT / GM_BM), 256>>>(
        pH, W2, b2, nullptr, nullptr, nullptr, nullptr, pX1, out, DFF, CDEC);
}